// round 7
// baseline (speedup 1.0000x reference)
#include <cuda_runtime.h>
#include <cuda_bf16.h>
#include <math.h>
#include <stdint.h>

// ---------------------------------------------------------------------------
// Problem constants: B=2, S=2048, D=1024, H=16, dh=64
// ---------------------------------------------------------------------------
#define B_  2
#define S_  2048
#define D_  1024
#define H_  16
#define DH_ 64
#define M_TOK (B_ * S_)          // 4096 tokens

// Scratch
__device__ float g_qkv[M_TOK * 3 * D_];    // qkv activations (tf32-exact)
__device__ float g_attn[M_TOK * D_];       // attention output (tf32-exact)
__device__ float g_x[M_TOK * D_];          // tf32-rounded x
__device__ float g_wqkv[3 * D_ * D_];      // tf32-rounded w_qkv^T  [3D][D]
__device__ float g_wout[D_ * D_];          // tf32-rounded w_out^T  [D][D]

// ---------------------------------------------------------------------------
// Helpers
// ---------------------------------------------------------------------------
__device__ __forceinline__ uint32_t smem_u32(const void* p) {
    return (uint32_t)__cvta_generic_to_shared(p);
}
__device__ __forceinline__ void cp_async16(uint32_t dst, const void* src) {
    asm volatile("cp.async.cg.shared.global [%0], [%1], 16;\n" :: "r"(dst), "l"(src));
}
__device__ __forceinline__ void cp_commit() {
    asm volatile("cp.async.commit_group;\n" ::: "memory");
}
__device__ __forceinline__ void cp_wait0() {
    asm volatile("cp.async.wait_group 0;\n" ::: "memory");
}
__device__ __forceinline__ void cp_wait1() {
    asm volatile("cp.async.wait_group 1;\n" ::: "memory");
}
__device__ __forceinline__ float round_tf32(float v) {
    uint32_t r;
    asm("cvt.rna.tf32.f32 %0, %1;" : "=r"(r) : "f"(v));
    return __uint_as_float(r);
}
// NOTE on k-slot permutation: for all mma below, hw k-slot tg maps to memory
// column (2*tg) and slot tg+4 to column (2*tg+1). A and B operands use the
// same mapping, so the reduction result is unchanged, but every fragment
// load becomes a contiguous float2 (LDS.64).
__device__ __forceinline__ void mma_tf32_16x8x8(
    float* c,
    uint32_t a0, uint32_t a1, uint32_t a2, uint32_t a3,
    uint32_t b0, uint32_t b1)
{
    asm volatile(
        "mma.sync.aligned.m16n8k8.row.col.f32.tf32.tf32.f32 "
        "{%0,%1,%2,%3}, {%4,%5,%6,%7}, {%8,%9}, {%0,%1,%2,%3};\n"
        : "+f"(c[0]), "+f"(c[1]), "+f"(c[2]), "+f"(c[3])
        : "r"(a0), "r"(a1), "r"(a2), "r"(a3), "r"(b0), "r"(b1));
}

// ---------------------------------------------------------------------------
// Elementwise tf32 pre-rounding (grid-stride float4)
// ---------------------------------------------------------------------------
__global__ void round_tf32_kernel(const float* __restrict__ in,
                                  float* __restrict__ out, int n4)
{
    for (int i = blockIdx.x * blockDim.x + threadIdx.x; i < n4;
         i += gridDim.x * blockDim.x) {
        float4 v = ((const float4*)in)[i];
        v.x = round_tf32(v.x); v.y = round_tf32(v.y);
        v.z = round_tf32(v.z); v.w = round_tf32(v.w);
        ((float4*)out)[i] = v;
    }
}

// Transpose + tf32 round: in[R][C] -> out[C][R]
__global__ void transpose_tf32_kernel(const float* __restrict__ in,
                                      float* __restrict__ out, int R, int C)
{
    __shared__ float t[32][33];
    const int bx = blockIdx.x * 32;
    const int by = blockIdx.y * 32;
    const int x = threadIdx.x, y = threadIdx.y;  // 32 x 8
#pragma unroll
    for (int i = 0; i < 32; i += 8)
        t[y + i][x] = round_tf32(in[(size_t)(by + y + i) * C + bx + x]);
    __syncthreads();
#pragma unroll
    for (int i = 0; i < 32; i += 8)
        out[(size_t)(bx + y + i) * R + by + x] = t[x][y + i];
}

// ---------------------------------------------------------------------------
// TF32 tensor-core GEMM: C[M,N] = A[M,K] @ Bt[N,K]^T  (both k-major).
// Block 128x128, BK=32, 256 threads = 8 warps (4m x 2n), warp tile 32x64.
// A/B smem rows padded to stride 40 (== 8 mod 32 -> LDS.64 conflict-free).
// ---------------------------------------------------------------------------
#define GBM 128
#define GBN 128
#define GBK 32
#define TST 40
#define T_BUF (128 * TST)
#define GEMM_SMEM (4 * T_BUF * sizeof(float))   // 81920 B

__global__ __launch_bounds__(256, 2) void mma_gemm_kernel(
    const float* __restrict__ A, const float* __restrict__ Bt,
    float* __restrict__ C, int M, int N, int K, int round_out)
{
    extern __shared__ float sm[];
    float* As = sm;                 // [2][128][40]
    float* Bs = sm + 2 * T_BUF;     // [2][128][40]  (rows = N, cols = K)

    const int tid  = threadIdx.x;
    const int warp = tid >> 5;
    const int lane = tid & 31;
    const int g    = lane >> 2;
    const int tg   = lane & 3;

    const int bm = blockIdx.y * GBM;
    const int bn = blockIdx.x * GBN;
    const int wm = (warp & 3) * 32;
    const int wn = (warp >> 2) * 64;

    float c[2][8][4];
#pragma unroll
    for (int mt = 0; mt < 2; mt++)
#pragma unroll
        for (int nt = 0; nt < 8; nt++)
#pragma unroll
            for (int i = 0; i < 4; i++) c[mt][nt][i] = 0.f;

    auto load_tiles = [&](int k0, int buf) {
        float* Ab = As + buf * T_BUF;
        float* Bb = Bs + buf * T_BUF;
#pragma unroll
        for (int it = 0; it < 4; ++it) {
            int idx = tid + it * 256;
            int r = idx >> 3, c4 = idx & 7;
            cp_async16(smem_u32(&Ab[r * TST + c4 * 4]),
                       &A[(size_t)(bm + r) * K + k0 + c4 * 4]);
        }
#pragma unroll
        for (int it = 0; it < 4; ++it) {
            int idx = tid + it * 256;
            int r = idx >> 3, c4 = idx & 7;
            cp_async16(smem_u32(&Bb[r * TST + c4 * 4]),
                       &Bt[(size_t)(bn + r) * K + k0 + c4 * 4]);
        }
        cp_commit();
    };

    load_tiles(0, 0);

    const int n_k = K / GBK;
    for (int kt = 0; kt < n_k; ++kt) {
        const int buf = kt & 1;
        if (kt + 1 < n_k) {
            load_tiles((kt + 1) * GBK, buf ^ 1);
            cp_wait1();
        } else {
            cp_wait0();
        }
        __syncthreads();

        const float* Ab = As + buf * T_BUF;
        const float* Bb = Bs + buf * T_BUF;

#pragma unroll
        for (int kk = 0; kk < GBK; kk += 8) {
            uint32_t a[2][4];
#pragma unroll
            for (int mt = 0; mt < 2; mt++) {
                const int r0 = wm + mt * 16 + g;
                float2 lo = *(const float2*)&Ab[(r0)     * TST + kk + 2 * tg];
                float2 hi = *(const float2*)&Ab[(r0 + 8) * TST + kk + 2 * tg];
                a[mt][0] = __float_as_uint(lo.x);
                a[mt][1] = __float_as_uint(hi.x);
                a[mt][2] = __float_as_uint(lo.y);
                a[mt][3] = __float_as_uint(hi.y);
            }
#pragma unroll
            for (int nt = 0; nt < 8; nt++) {
                const int col = wn + nt * 8 + g;
                float2 bv = *(const float2*)&Bb[(size_t)col * TST + kk + 2 * tg];
                uint32_t b0 = __float_as_uint(bv.x);
                uint32_t b1 = __float_as_uint(bv.y);
#pragma unroll
                for (int mt = 0; mt < 2; mt++) {
                    mma_tf32_16x8x8(c[mt][nt],
                                    a[mt][0], a[mt][1], a[mt][2], a[mt][3],
                                    b0, b1);
                }
            }
        }
        __syncthreads();
    }

#pragma unroll
    for (int mt = 0; mt < 2; mt++) {
        const int r0 = bm + wm + mt * 16 + g;
#pragma unroll
        for (int nt = 0; nt < 8; nt++) {
            const int col = bn + wn + nt * 8 + tg * 2;
            float v0 = c[mt][nt][0], v1 = c[mt][nt][1];
            float v2 = c[mt][nt][2], v3 = c[mt][nt][3];
            if (round_out) {
                v0 = round_tf32(v0); v1 = round_tf32(v1);
                v2 = round_tf32(v2); v3 = round_tf32(v3);
            }
            *(float2*)&C[(size_t)r0 * N + col]       = make_float2(v0, v1);
            *(float2*)&C[(size_t)(r0 + 8) * N + col] = make_float2(v2, v3);
        }
    }
}

// ---------------------------------------------------------------------------
// Flash attention (TF32 mma.sync), float2 fragment loads via k-slot permute.
// Strides: QP 72, K 72, V 68 (all chosen conflict-free for their patterns).
// ---------------------------------------------------------------------------
#define AT_Q 128
#define AT_K 64
#define KD 72
#define VD 68
#define PD 72
#define QP_FLOATS (AT_Q * PD)                  // 9216
#define K_FLOATS  (AT_K * KD)                  // 4608
#define V_FLOATS  (AT_K * VD)                  // 4352
#define ATTN_SMEM ((QP_FLOATS + 2 * K_FLOATS + 2 * V_FLOATS) * sizeof(float)) // 108544
#define NEG_INF_F (-1e30f)

__global__ __launch_bounds__(256, 2) void attn_kernel(
    const float* __restrict__ qkv, float* __restrict__ out)
{
    const int qt   = (int)gridDim.x - 1 - (int)blockIdx.x;  // heavy first
    const int h    = blockIdx.y;
    const int b    = blockIdx.z;
    const int tid  = threadIdx.x;
    const int warp = tid >> 5;
    const int lane = tid & 31;
    const int g    = lane >> 2;
    const int tg   = lane & 3;
    const int wm   = warp * 16;

    extern __shared__ float sm[];
    float* QP = sm;
    float* Ks = sm + QP_FLOATS;
    float* Vs = sm + QP_FLOATS + 2 * K_FLOATS;

    const float scale = 0.125f;
    const size_t base = (size_t)b * S_ * 3 * D_ + (size_t)h * DH_;

    {
#pragma unroll
        for (int it = 0; it < 8; ++it) {
            int idx = tid + it * 256;
            int r = idx >> 4, c4 = idx & 15;
            cp_async16(smem_u32(&QP[r * PD + c4 * 4]),
                       &qkv[base + (size_t)(qt * AT_Q + r) * 3 * D_ + c4 * 4]);
        }
#pragma unroll
        for (int it = 0; it < 4; ++it) {
            int idx = tid + it * 256;
            int r = idx >> 4, c4 = idx & 15;
            size_t gsrc = base + (size_t)r * 3 * D_ + c4 * 4;
            cp_async16(smem_u32(&Ks[r * KD + c4 * 4]), &qkv[gsrc + D_]);
            cp_async16(smem_u32(&Vs[r * VD + c4 * 4]), &qkv[gsrc + 2 * D_]);
        }
        cp_commit();
    }

    uint32_t qa[8][4];
    float o[8][4];
    float m0 = NEG_INF_F, m1 = NEG_INF_F, l0 = 0.f, l1 = 0.f;
#pragma unroll
    for (int nt = 0; nt < 8; nt++)
#pragma unroll
        for (int i = 0; i < 4; i++) o[nt][i] = 0.f;

    const int n_tiles = 2 * qt + 2;
    for (int kt = 0; kt < n_tiles; ++kt) {
        const int buf = kt & 1;
        if (kt > 0) __syncthreads();

        if (kt + 1 < n_tiles) {
            float* Kn = &Ks[(size_t)(buf ^ 1) * K_FLOATS];
            float* Vn = &Vs[(size_t)(buf ^ 1) * V_FLOATS];
#pragma unroll
            for (int it = 0; it < 4; ++it) {
                int idx = tid + it * 256;
                int r = idx >> 4, c4 = idx & 15;
                size_t gsrc = base + (size_t)((kt + 1) * AT_K + r) * 3 * D_ + c4 * 4;
                cp_async16(smem_u32(&Kn[r * KD + c4 * 4]), &qkv[gsrc + D_]);
                cp_async16(smem_u32(&Vn[r * VD + c4 * 4]), &qkv[gsrc + 2 * D_]);
            }
            cp_commit();
            cp_wait1();
        } else {
            cp_wait0();
        }
        __syncthreads();

        if (kt == 0) {
#pragma unroll
            for (int k8 = 0; k8 < 8; k8++) {
                const int kk = k8 * 8;
                float2 lo = *(const float2*)&QP[(wm + g)     * PD + kk + 2 * tg];
                float2 hi = *(const float2*)&QP[(wm + g + 8) * PD + kk + 2 * tg];
                qa[k8][0] = __float_as_uint(lo.x);
                qa[k8][1] = __float_as_uint(hi.x);
                qa[k8][2] = __float_as_uint(lo.y);
                qa[k8][3] = __float_as_uint(hi.y);
            }
        }

        const float* Kb = &Ks[(size_t)buf * K_FLOATS];
        const float* Vb = &Vs[(size_t)buf * V_FLOATS];

        // ---- S = Q @ K^T ----
        float s[8][4];
#pragma unroll
        for (int nt = 0; nt < 8; nt++)
#pragma unroll
            for (int i = 0; i < 4; i++) s[nt][i] = 0.f;

#pragma unroll
        for (int k8 = 0; k8 < 8; k8++) {
            const int kk = k8 * 8;
#pragma unroll
            for (int nt = 0; nt < 8; nt++) {
                float2 bv = *(const float2*)&Kb[(nt * 8 + g) * KD + kk + 2 * tg];
                mma_tf32_16x8x8(s[nt], qa[k8][0], qa[k8][1], qa[k8][2], qa[k8][3],
                                __float_as_uint(bv.x), __float_as_uint(bv.y));
            }
        }

        // ---- mask + scale + online softmax ----
        const int grow0 = qt * AT_Q + wm + g;
        const int grow1 = grow0 + 8;
        const bool interior = (kt * AT_K + AT_K - 1 <= qt * AT_Q + wm);

        float mx0 = NEG_INF_F, mx1 = NEG_INF_F;
#pragma unroll
        for (int nt = 0; nt < 8; nt++) {
            const int gc0 = kt * AT_K + nt * 8 + 2 * tg;
            s[nt][0] = (interior || gc0     <= grow0) ? s[nt][0] * scale : NEG_INF_F;
            s[nt][1] = (interior || gc0 + 1 <= grow0) ? s[nt][1] * scale : NEG_INF_F;
            s[nt][2] = (interior || gc0     <= grow1) ? s[nt][2] * scale : NEG_INF_F;
            s[nt][3] = (interior || gc0 + 1 <= grow1) ? s[nt][3] * scale : NEG_INF_F;
            mx0 = fmaxf(mx0, fmaxf(s[nt][0], s[nt][1]));
            mx1 = fmaxf(mx1, fmaxf(s[nt][2], s[nt][3]));
        }
        mx0 = fmaxf(mx0, __shfl_xor_sync(0xffffffffu, mx0, 1));
        mx0 = fmaxf(mx0, __shfl_xor_sync(0xffffffffu, mx0, 2));
        mx1 = fmaxf(mx1, __shfl_xor_sync(0xffffffffu, mx1, 1));
        mx1 = fmaxf(mx1, __shfl_xor_sync(0xffffffffu, mx1, 2));

        const float mn0 = fmaxf(m0, mx0);
        const float mn1 = fmaxf(m1, mx1);
        const float cr0 = __expf(m0 - mn0);
        const float cr1 = __expf(m1 - mn1);
        m0 = mn0; m1 = mn1;

        float sum0 = 0.f, sum1 = 0.f;
#pragma unroll
        for (int nt = 0; nt < 8; nt++) {
            s[nt][0] = __expf(s[nt][0] - mn0);
            s[nt][1] = __expf(s[nt][1] - mn0);
            s[nt][2] = __expf(s[nt][2] - mn1);
            s[nt][3] = __expf(s[nt][3] - mn1);
            sum0 += s[nt][0] + s[nt][1];
            sum1 += s[nt][2] + s[nt][3];
        }
        sum0 += __shfl_xor_sync(0xffffffffu, sum0, 1);
        sum0 += __shfl_xor_sync(0xffffffffu, sum0, 2);
        sum1 += __shfl_xor_sync(0xffffffffu, sum1, 1);
        sum1 += __shfl_xor_sync(0xffffffffu, sum1, 2);
        l0 = l0 * cr0 + sum0;
        l1 = l1 * cr1 + sum1;

#pragma unroll
        for (int nt = 0; nt < 8; nt++) {
            o[nt][0] *= cr0; o[nt][1] *= cr0;
            o[nt][2] *= cr1; o[nt][3] *= cr1;
        }

        // ---- stage P (tf32) in warp-private rows ----
#pragma unroll
        for (int nt = 0; nt < 8; nt++) {
            *(float2*)&QP[(wm + g)     * PD + nt * 8 + 2 * tg] =
                make_float2(round_tf32(s[nt][0]), round_tf32(s[nt][1]));
            *(float2*)&QP[(wm + g + 8) * PD + nt * 8 + 2 * tg] =
                make_float2(round_tf32(s[nt][2]), round_tf32(s[nt][3]));
        }
        __syncwarp();

        // ---- O += P @ V ----
#pragma unroll
        for (int k8 = 0; k8 < 8; k8++) {
            const int kk = k8 * 8;
            float2 plo = *(const float2*)&QP[(wm + g)     * PD + kk + 2 * tg];
            float2 phi = *(const float2*)&QP[(wm + g + 8) * PD + kk + 2 * tg];
            uint32_t a0 = __float_as_uint(plo.x);
            uint32_t a1 = __float_as_uint(phi.x);
            uint32_t a2 = __float_as_uint(plo.y);
            uint32_t a3 = __float_as_uint(phi.y);
#pragma unroll
            for (int nt = 0; nt < 8; nt++) {
                uint32_t b0 = __float_as_uint(Vb[(kk + 2 * tg)     * VD + nt * 8 + g]);
                uint32_t b1 = __float_as_uint(Vb[(kk + 2 * tg + 1) * VD + nt * 8 + g]);
                mma_tf32_16x8x8(o[nt], a0, a1, a2, a3, b0, b1);
            }
        }
    }

    const float inv0 = 1.f / l0;
    const float inv1 = 1.f / l1;
    const size_t row0 = (size_t)(b * S_ + qt * AT_Q + wm + g);
#pragma unroll
    for (int nt = 0; nt < 8; nt++) {
        const int col = h * DH_ + nt * 8 + 2 * tg;
        *(float2*)&out[row0 * D_ + col] =
            make_float2(round_tf32(o[nt][0] * inv0), round_tf32(o[nt][1] * inv0));
        *(float2*)&out[(row0 + 8) * D_ + col] =
            make_float2(round_tf32(o[nt][2] * inv1), round_tf32(o[nt][3] * inv1));
    }
}

// ---------------------------------------------------------------------------
// Launch
// ---------------------------------------------------------------------------
extern "C" void kernel_launch(void* const* d_in, const int* in_sizes, int n_in,
                              void* d_out, int out_size)
{
    const float* x     = (const float*)d_in[0];   // [4096,1024]
    const float* w_qkv = (const float*)d_in[1];   // [1024,3072]
    const float* w_out = (const float*)d_in[2];   // [1024,1024]
    float* out = (float*)d_out;                   // [4096,1024]

    float *qkv, *attn, *xr, *wqkvr, *woutr;
    cudaGetSymbolAddress((void**)&qkv,   g_qkv);
    cudaGetSymbolAddress((void**)&attn,  g_attn);
    cudaGetSymbolAddress((void**)&xr,    g_x);
    cudaGetSymbolAddress((void**)&wqkvr, g_wqkv);
    cudaGetSymbolAddress((void**)&woutr, g_wout);

    // 0) tf32-round x; transpose+round weights to [N][K]
    round_tf32_kernel<<<592, 256>>>(x, xr, M_TOK * D_ / 4);
    {
        dim3 blk(32, 8);
        dim3 g1(3 * D_ / 32, D_ / 32);
        transpose_tf32_kernel<<<g1, blk>>>(w_qkv, wqkvr, D_, 3 * D_);
        dim3 g2(D_ / 32, D_ / 32);
        transpose_tf32_kernel<<<g2, blk>>>(w_out, woutr, D_, D_);
    }

    // 1) QKV projection (tf32 TC), epilogue rounds to tf32 for attention
    {
        cudaFuncSetAttribute(mma_gemm_kernel,
                             cudaFuncAttributeMaxDynamicSharedMemorySize,
                             (int)GEMM_SMEM);
        dim3 grid(3 * D_ / GBN, M_TOK / GBM);
        mma_gemm_kernel<<<grid, 256, GEMM_SMEM>>>(xr, wqkvr, qkv, M_TOK, 3 * D_, D_, 1);
    }

    // 2) Flash attention (tf32 TC)
    {
        cudaFuncSetAttribute(attn_kernel,
                             cudaFuncAttributeMaxDynamicSharedMemorySize,
                             (int)ATTN_SMEM);
        dim3 grid(S_ / AT_Q, H_, B_);
        attn_kernel<<<grid, 256, ATTN_SMEM>>>(qkv, attn);
    }

    // 3) Output projection (tf32 TC)
    {
        dim3 grid(D_ / GBN, M_TOK / GBM);
        mma_gemm_kernel<<<grid, 256, GEMM_SMEM>>>(attn, woutr, out, M_TOK, D_, D_, 0);
    }
}